// round 6
// baseline (speedup 1.0000x reference)
#include <cuda_runtime.h>
#include <cuda_bf16.h>
#include <cstdint>

#define BB 32768
#define NI 256
#define NH 1024
#define NF 256

// ---------------- scratch (device globals; no allocs allowed) ----------------
__device__ __align__(16) __nv_bfloat16 g_a_hi[(size_t)BB * NI];
__device__ __align__(16) __nv_bfloat16 g_a_lo[(size_t)BB * NI];
__device__ __align__(16) __nv_bfloat16 g_w1_hi[NH * NI];
__device__ __align__(16) __nv_bfloat16 g_w1_lo[NH * NI];
__device__ __align__(16) __nv_bfloat16 g_w2_hi[NF * NH];
__device__ __align__(16) __nv_bfloat16 g_w2_lo[NF * NH];
__device__ __align__(16) __nv_bfloat16 g_h_hi[(size_t)BB * NH];
__device__ __align__(16) __nv_bfloat16 g_h_lo[(size_t)BB * NH];
__device__ __align__(16) float g_p[(size_t)BB * NF];

__device__ __forceinline__ uint32_t smem_u32(const void* p) {
    uint32_t a;
    asm("{ .reg .u64 t; cvta.to.shared.u64 t, %1; cvt.u32.u64 %0, t; }" : "=r"(a) : "l"(p));
    return a;
}
__device__ __forceinline__ void cp16(uint32_t saddr, const void* gaddr) {
    asm volatile("cp.async.cg.shared.global [%0], [%1], 16;\n" :: "r"(saddr), "l"(gaddr));
}
__device__ __forceinline__ void cp_commit() {
    asm volatile("cp.async.commit_group;\n" ::: "memory");
}
template <int N>
__device__ __forceinline__ void cp_wait() {
    asm volatile("cp.async.wait_group %0;\n" :: "n"(N) : "memory");
}
__device__ __forceinline__ void ldmx4(uint32_t* r, uint32_t addr) {
    asm volatile("ldmatrix.sync.aligned.m8n8.x4.shared.b16 {%0,%1,%2,%3}, [%4];"
                 : "=r"(r[0]), "=r"(r[1]), "=r"(r[2]), "=r"(r[3]) : "r"(addr));
}
__device__ __forceinline__ void mma16816(float* d, const uint32_t* a, uint32_t b0, uint32_t b1) {
    asm volatile(
        "mma.sync.aligned.m16n8k16.row.col.f32.bf16.bf16.f32 "
        "{%0,%1,%2,%3}, {%4,%5,%6,%7}, {%8,%9}, {%0,%1,%2,%3};"
        : "+f"(d[0]), "+f"(d[1]), "+f"(d[2]), "+f"(d[3])
        : "r"(a[0]), "r"(a[1]), "r"(a[2]), "r"(a[3]), "r"(b0), "r"(b1));
}

// ---------------- hi/lo split kernels ----------------
__global__ __launch_bounds__(256) void split_x(const float* __restrict__ x,
                                               __nv_bfloat16* __restrict__ hi,
                                               __nv_bfloat16* __restrict__ lo) {
    int i = blockIdx.x * 256 + threadIdx.x;           // i < BB*NI
    int r = i >> 8, c = i & 255;
    float v = x[(size_t)r * 257 + c];
    __nv_bfloat16 h = __float2bfloat16(v);
    hi[i] = h;
    lo[i] = __float2bfloat16(v - __bfloat162float(h));
}
__global__ __launch_bounds__(256) void split_w(const float* __restrict__ w,
                                               __nv_bfloat16* __restrict__ hi,
                                               __nv_bfloat16* __restrict__ lo, int n) {
    int i = blockIdx.x * 256 + threadIdx.x;
    if (i < n) {
        float v = w[i];
        __nv_bfloat16 h = __float2bfloat16(v);
        hi[i] = h;
        lo[i] = __float2bfloat16(v - __bfloat162float(h));
    }
}

// ---------------- HMMA GEMM (mma.sync m16n8k16 bf16, 3-pass hi/lo) ----------
// C[M,N] = A[M,K] @ B[N,K]^T + bias.  CTA tile 128x128x32, 4 warps (2x2),
// warp tile 64x64.  2-stage cp.async double buffer, 1 sync/iter, 2 CTAs/SM.
// MODE 0: fp32 out.  MODE 1: relu + bf16 hi/lo out.
constexpr int PITCH = 80;                 // 64B data + 16B pad per row
constexpr int TILE  = 128 * PITCH;        // 10240 B
constexpr int STAGE = 4 * TILE;           // 40960 B (Ah,Al,Bh,Bl)
constexpr int SMEM_BYTES = 2 * STAGE;     // 81920 B  -> 2 CTAs/SM

template <int MODE>
__global__ __launch_bounds__(128, 2) void hmma_gemm(
    const __nv_bfloat16* __restrict__ Ah, const __nv_bfloat16* __restrict__ Al,
    const __nv_bfloat16* __restrict__ Bh, const __nv_bfloat16* __restrict__ Bl,
    const float* __restrict__ bias, int K, int ldc,
    float* __restrict__ Cf,
    __nv_bfloat16* __restrict__ Chi, __nv_bfloat16* __restrict__ Clo)
{
    extern __shared__ __align__(128) char smem[];
    const uint32_t sb = smem_u32(smem);
    const int tid = threadIdx.x;
    const int w = tid >> 5, lane = tid & 31;
    const int wm = w >> 1, wn = w & 1;        // 2x2 warp grid, 64x64 tiles
    const int gid = lane >> 2, tig = lane & 3;
    const int m0 = blockIdx.y * 128, n0 = blockIdx.x * 128;

    float acc[4][8][4];
#pragma unroll
    for (int i = 0; i < 4; i++)
#pragma unroll
        for (int j = 0; j < 8; j++)
#pragma unroll
            for (int t = 0; t < 4; t++) acc[i][j][t] = 0.f;

    const int lrow = tid >> 2;           // 0..31; rows lrow + 32*t2
    const int lch  = tid & 3;

    auto load_stage = [&](int s, int c) {
        const uint32_t st = sb + s * STAGE;
        const int k0 = c * 32;
#pragma unroll
        for (int t2 = 0; t2 < 4; t2++) {
            int row = lrow + t2 * 32;
            uint32_t so = st + row * PITCH + lch * 16;
            size_t goffA = (size_t)(m0 + row) * K + k0 + lch * 8;
            size_t goffB = (size_t)(n0 + row) * K + k0 + lch * 8;
            cp16(so,            Ah + goffA);
            cp16(so + TILE,     Al + goffA);
            cp16(so + 2 * TILE, Bh + goffB);
            cp16(so + 3 * TILE, Bl + goffB);
        }
    };

    auto compute_stage = [&](int s) {
        const uint32_t st = sb + s * STAGE;
        const uint32_t lsel = (lane & 15), hsel = (lane >> 4);
#pragma unroll
        for (int ks = 0; ks < 2; ks++) {
            uint32_t a_off = st + (wm * 64 + lsel) * PITCH + ks * 32 + hsel * 16;
            uint32_t b_off = st + 2 * TILE + (wn * 64 + lsel) * PITCH + ks * 32 + hsel * 16;
            uint32_t bh[4][4], bl[4][4];
#pragma unroll
            for (int p = 0; p < 4; p++) ldmx4(bh[p], b_off + p * 16 * PITCH);
#pragma unroll
            for (int p = 0; p < 4; p++) ldmx4(bl[p], b_off + p * 16 * PITCH + TILE);
#pragma unroll
            for (int i = 0; i < 4; i++) {
                uint32_t ah[4], al[4];
                ldmx4(ah, a_off + i * 16 * PITCH);
                ldmx4(al, a_off + i * 16 * PITCH + TILE);
#pragma unroll
                for (int j = 0; j < 8; j++) {
                    const int p = j >> 1, r = j & 1;
                    mma16816(acc[i][j], ah, bh[p][r], bh[p][r + 2]);
                    mma16816(acc[i][j], ah, bl[p][r], bl[p][r + 2]);
                    mma16816(acc[i][j], al, bh[p][r], bh[p][r + 2]);
                }
            }
        }
    };

    const int C = K >> 5;
    load_stage(0, 0); cp_commit();
    for (int c = 0; c < C; c++) {
        cp_wait<0>();
        __syncthreads();
        if (c + 1 < C) { load_stage((c + 1) & 1, c + 1); cp_commit(); }
        compute_stage(c & 1);
    }

    // epilogue
    const int mr = m0 + wm * 64;
    const int nc = n0 + wn * 64;
#pragma unroll
    for (int i = 0; i < 4; i++) {
#pragma unroll
        for (int j = 0; j < 8; j++) {
            int n = nc + j * 8 + tig * 2;
            float2 bv = *(const float2*)(bias + n);
            int r_lo = mr + i * 16 + gid;
            int r_hi = r_lo + 8;
            float v00 = acc[i][j][0] + bv.x, v01 = acc[i][j][1] + bv.y;
            float v10 = acc[i][j][2] + bv.x, v11 = acc[i][j][3] + bv.y;
            if (MODE == 1) {
                v00 = fmaxf(v00, 0.f); v01 = fmaxf(v01, 0.f);
                v10 = fmaxf(v10, 0.f); v11 = fmaxf(v11, 0.f);
                __nv_bfloat16 h00 = __float2bfloat16(v00), h01 = __float2bfloat16(v01);
                __nv_bfloat16 h10 = __float2bfloat16(v10), h11 = __float2bfloat16(v11);
                __nv_bfloat162 hi0(h00, h01), hi1(h10, h11);
                __nv_bfloat162 lo0(__float2bfloat16(v00 - __bfloat162float(h00)),
                                   __float2bfloat16(v01 - __bfloat162float(h01)));
                __nv_bfloat162 lo1(__float2bfloat16(v10 - __bfloat162float(h10)),
                                   __float2bfloat16(v11 - __bfloat162float(h11)));
                *(__nv_bfloat162*)(Chi + (size_t)r_lo * ldc + n) = hi0;
                *(__nv_bfloat162*)(Chi + (size_t)r_hi * ldc + n) = hi1;
                *(__nv_bfloat162*)(Clo + (size_t)r_lo * ldc + n) = lo0;
                *(__nv_bfloat162*)(Clo + (size_t)r_hi * ldc + n) = lo1;
            } else {
                *(float2*)(Cf + (size_t)r_lo * ldc + n) = make_float2(v00, v01);
                *(float2*)(Cf + (size_t)r_hi * ldc + n) = make_float2(v10, v11);
            }
        }
    }
}

// ---------------- convex fixed-point + gather (warp per row) ----------------
__global__ __launch_bounds__(256) void convex_gather(
    const float* __restrict__ p, const float* __restrict__ x, float* __restrict__ out) {
    const unsigned FULL = 0xffffffffu;
    int warp = (blockIdx.x * blockDim.x + threadIdx.x) >> 5;
    int lane = threadIdx.x & 31;
    if (warp >= BB) return;

    const float* row = p + (size_t)warp * NF;
    float e[8];
    {
        float4 v0 = *(const float4*)(row + lane * 8);
        float4 v1 = *(const float4*)(row + lane * 8 + 4);
        e[0] = v0.x; e[1] = v0.y; e[2] = v0.z; e[3] = v0.w;
        e[4] = v1.x; e[5] = v1.y; e[6] = v1.z; e[7] = v1.w;
    }
#pragma unroll 2
    for (int it = 0; it < 100; ++it) {
        float lin = __shfl_up_sync(FULL, e[7], 1);
        float rin = __shfl_down_sync(FULL, e[0], 1);
        float n0 = fminf(e[0], 0.5f * (lin + e[1]));
        float n1 = fminf(e[1], 0.5f * (e[0] + e[2]));
        float n2 = fminf(e[2], 0.5f * (e[1] + e[3]));
        float n3 = fminf(e[3], 0.5f * (e[2] + e[4]));
        float n4 = fminf(e[4], 0.5f * (e[3] + e[5]));
        float n5 = fminf(e[5], 0.5f * (e[4] + e[6]));
        float n6 = fminf(e[6], 0.5f * (e[5] + e[7]));
        float n7 = fminf(e[7], 0.5f * (e[6] + rin));
        if (lane == 0)  n0 = e[0];
        if (lane == 31) n7 = e[7];
        e[0] = n0; e[1] = n1; e[2] = n2; e[3] = n3;
        e[4] = n4; e[5] = n5; e[6] = n6; e[7] = n7;
    }
    float q = x[(size_t)warp * 257 + 256];
    int idx = (int)rintf(q * 255.0f);
    idx = min(max(idx, 0), 255);
    int src_lane = idx >> 3, sub = idx & 7;
    float val = 0.f;
#pragma unroll
    for (int j = 0; j < 8; j++) {
        float t = __shfl_sync(FULL, e[j], src_lane);
        if (j == sub) val = t;
    }
    if (lane == 0) out[warp] = val;
}

// ---------------- launch ----------------
extern "C" void kernel_launch(void* const* d_in, const int* in_sizes, int n_in,
                              void* d_out, int out_size) {
    const float* x  = (const float*)d_in[0];
    const float* W1 = (const float*)d_in[1];
    const float* b1 = (const float*)d_in[2];
    const float* W2 = (const float*)d_in[3];
    const float* b2 = (const float*)d_in[4];
    float* out = (float*)d_out;

    void *pa_hi, *pa_lo, *pw1h, *pw1l, *pw2h, *pw2l, *phh, *phl, *pp;
    cudaGetSymbolAddress(&pa_hi, g_a_hi); cudaGetSymbolAddress(&pa_lo, g_a_lo);
    cudaGetSymbolAddress(&pw1h, g_w1_hi); cudaGetSymbolAddress(&pw1l, g_w1_lo);
    cudaGetSymbolAddress(&pw2h, g_w2_hi); cudaGetSymbolAddress(&pw2l, g_w2_lo);
    cudaGetSymbolAddress(&phh, g_h_hi);   cudaGetSymbolAddress(&phl, g_h_lo);
    cudaGetSymbolAddress(&pp, g_p);

    __nv_bfloat16 *a_hi = (__nv_bfloat16*)pa_hi, *a_lo = (__nv_bfloat16*)pa_lo;
    __nv_bfloat16 *w1h = (__nv_bfloat16*)pw1h, *w1l = (__nv_bfloat16*)pw1l;
    __nv_bfloat16 *w2h = (__nv_bfloat16*)pw2h, *w2l = (__nv_bfloat16*)pw2l;
    __nv_bfloat16 *hh = (__nv_bfloat16*)phh, *hl = (__nv_bfloat16*)phl;
    float* prm = (float*)pp;

    cudaFuncSetAttribute(hmma_gemm<0>, cudaFuncAttributeMaxDynamicSharedMemorySize, SMEM_BYTES);
    cudaFuncSetAttribute(hmma_gemm<1>, cudaFuncAttributeMaxDynamicSharedMemorySize, SMEM_BYTES);

    split_x<<<BB * NI / 256, 256>>>(x, a_hi, a_lo);
    split_w<<<NH * NI / 256, 256>>>(W1, w1h, w1l, NH * NI);
    split_w<<<NF * NH / 256, 256>>>(W2, w2h, w2l, NF * NH);

    // GEMM1: h = relu(x @ W1^T + b1) -> bf16 hi/lo
    hmma_gemm<1><<<dim3(NH / 128, BB / 128), 128, SMEM_BYTES>>>(
        a_hi, a_lo, w1h, w1l, b1, NI, NH, nullptr, hh, hl);
    // GEMM2: prm = h @ W2^T + b2 (fp32)
    hmma_gemm<0><<<dim3(NF / 128, BB / 128), 128, SMEM_BYTES>>>(
        hh, hl, w2h, w2l, b2, NH, NF, prm, nullptr, nullptr);

    convex_gather<<<BB / 8, 256>>>(prm, x, out);
}

// round 7
// speedup vs baseline: 1.0197x; 1.0197x over previous
#include <cuda_runtime.h>
#include <cuda_bf16.h>
#include <cstdint>

#define BB 32768
#define NI 256
#define NH 1024
#define NF 256

// ---------------- scratch (device globals; no allocs allowed) ----------------
__device__ __align__(16) __nv_bfloat16 g_a_hi[(size_t)BB * NI];
__device__ __align__(16) __nv_bfloat16 g_a_lo[(size_t)BB * NI];
__device__ __align__(16) __nv_bfloat16 g_w1_hi[NH * NI];
__device__ __align__(16) __nv_bfloat16 g_w1_lo[NH * NI];
__device__ __align__(16) __nv_bfloat16 g_w2_hi[NF * NH];
__device__ __align__(16) __nv_bfloat16 g_w2_lo[NF * NH];
__device__ __align__(16) __nv_bfloat16 g_h_hi[(size_t)BB * NH];
__device__ __align__(16) __nv_bfloat16 g_h_lo[(size_t)BB * NH];
__device__ __align__(16) float g_p[(size_t)BB * NF];

__device__ __forceinline__ uint32_t smem_u32(const void* p) {
    uint32_t a;
    asm("{ .reg .u64 t; cvta.to.shared.u64 t, %1; cvt.u32.u64 %0, t; }" : "=r"(a) : "l"(p));
    return a;
}
__device__ __forceinline__ void cp16(uint32_t saddr, const void* gaddr) {
    asm volatile("cp.async.cg.shared.global [%0], [%1], 16;\n" :: "r"(saddr), "l"(gaddr));
}
__device__ __forceinline__ void cp_commit() {
    asm volatile("cp.async.commit_group;\n" ::: "memory");
}
template <int N>
__device__ __forceinline__ void cp_wait() {
    asm volatile("cp.async.wait_group %0;\n" :: "n"(N) : "memory");
}
__device__ __forceinline__ void ldmx4(uint32_t* r, uint32_t addr) {
    asm volatile("ldmatrix.sync.aligned.m8n8.x4.shared.b16 {%0,%1,%2,%3}, [%4];"
                 : "=r"(r[0]), "=r"(r[1]), "=r"(r[2]), "=r"(r[3]) : "r"(addr));
}
__device__ __forceinline__ void mma16816(float* d, const uint32_t* a, uint32_t b0, uint32_t b1) {
    asm volatile(
        "mma.sync.aligned.m16n8k16.row.col.f32.bf16.bf16.f32 "
        "{%0,%1,%2,%3}, {%4,%5,%6,%7}, {%8,%9}, {%0,%1,%2,%3};"
        : "+f"(d[0]), "+f"(d[1]), "+f"(d[2]), "+f"(d[3])
        : "r"(a[0]), "r"(a[1]), "r"(a[2]), "r"(a[3]), "r"(b0), "r"(b1));
}

// ---------------- hi/lo split kernels ----------------
__global__ __launch_bounds__(256) void split_x(const float* __restrict__ x,
                                               __nv_bfloat16* __restrict__ hi,
                                               __nv_bfloat16* __restrict__ lo) {
    int i = blockIdx.x * 256 + threadIdx.x;           // i < BB*NI
    int r = i >> 8, c = i & 255;
    float v = x[(size_t)r * 257 + c];
    __nv_bfloat16 h = __float2bfloat16(v);
    hi[i] = h;
    lo[i] = __float2bfloat16(v - __bfloat162float(h));
}
__global__ __launch_bounds__(256) void split_w(const float* __restrict__ w,
                                               __nv_bfloat16* __restrict__ hi,
                                               __nv_bfloat16* __restrict__ lo, int n) {
    int i = blockIdx.x * 256 + threadIdx.x;
    if (i < n) {
        float v = w[i];
        __nv_bfloat16 h = __float2bfloat16(v);
        hi[i] = h;
        lo[i] = __float2bfloat16(v - __bfloat162float(h));
    }
}

// ---------------- HMMA GEMM (mma.sync m16n8k16 bf16, 3-pass hi/lo) ----------
// C[M,N] = A[M,K] @ B[N,K]^T + bias.  CTA tile 128x128x32, 8 warps (2x4),
// warp tile 64x32.  2-stage cp.async double buffer, 1 sync/iter, 2 CTAs/SM.
// Pass-major MMA order: same-acc dependent MMAs are distance-4 apart.
// MODE 0: fp32 out.  MODE 1: relu + bf16 hi/lo out.
constexpr int PITCH = 80;                 // 64B data + 16B pad per row
constexpr int TILE  = 128 * PITCH;        // 10240 B
constexpr int STAGE = 4 * TILE;           // 40960 B (Ah,Al,Bh,Bl)
constexpr int SMEM_BYTES = 2 * STAGE;     // 81920 B  -> 2 CTAs/SM

template <int MODE>
__global__ __launch_bounds__(256, 2) void hmma_gemm(
    const __nv_bfloat16* __restrict__ Ah, const __nv_bfloat16* __restrict__ Al,
    const __nv_bfloat16* __restrict__ Bh, const __nv_bfloat16* __restrict__ Bl,
    const float* __restrict__ bias, int K, int ldc,
    float* __restrict__ Cf,
    __nv_bfloat16* __restrict__ Chi, __nv_bfloat16* __restrict__ Clo)
{
    extern __shared__ __align__(128) char smem[];
    const uint32_t sb = smem_u32(smem);
    const int tid = threadIdx.x;
    const int w = tid >> 5, lane = tid & 31;
    const int wm = w >> 2, wn = w & 3;        // 2x4 warp grid
    const int gid = lane >> 2, tig = lane & 3;
    const int m0 = blockIdx.y * 128, n0 = blockIdx.x * 128;

    float acc[4][4][4];
#pragma unroll
    for (int i = 0; i < 4; i++)
#pragma unroll
        for (int j = 0; j < 4; j++)
#pragma unroll
            for (int t = 0; t < 4; t++) acc[i][j][t] = 0.f;

    const int lrow = tid >> 2;           // rows tid>>2 and (tid>>2)+64
    const int lch  = tid & 3;

    auto load_stage = [&](int s, int c) {
        const uint32_t st = sb + s * STAGE;
        const int k0 = c * 32;
#pragma unroll
        for (int t2 = 0; t2 < 2; t2++) {
            int row = lrow + t2 * 64;
            uint32_t so = st + row * PITCH + lch * 16;
            size_t goffA = (size_t)(m0 + row) * K + k0 + lch * 8;
            size_t goffB = (size_t)(n0 + row) * K + k0 + lch * 8;
            cp16(so,            Ah + goffA);
            cp16(so + TILE,     Al + goffA);
            cp16(so + 2 * TILE, Bh + goffB);
            cp16(so + 3 * TILE, Bl + goffB);
        }
    };

    auto compute_stage = [&](int s) {
        const uint32_t st = sb + s * STAGE;
        const uint32_t lsel = (lane & 15), hsel = (lane >> 4);
#pragma unroll
        for (int ks = 0; ks < 2; ks++) {
            uint32_t a_off = st + (wm * 64 + lsel) * PITCH + ks * 32 + hsel * 16;
            uint32_t b_off = st + 2 * TILE + (wn * 32 + lsel) * PITCH + ks * 32 + hsel * 16;
            uint32_t bh[2][4], bl[2][4];
#pragma unroll
            for (int p = 0; p < 2; p++) ldmx4(bh[p], b_off + p * 16 * PITCH);
#pragma unroll
            for (int p = 0; p < 2; p++) ldmx4(bl[p], b_off + p * 16 * PITCH + TILE);
#pragma unroll
            for (int i = 0; i < 4; i++) {
                uint32_t ah[4], al[4];
                ldmx4(ah, a_off + i * 16 * PITCH);
                ldmx4(al, a_off + i * 16 * PITCH + TILE);
                // pass-major: 4 independent MMAs per pass; same-acc deps are
                // 4 apart instead of back-to-back (asm volatile pins order).
#pragma unroll
                for (int j = 0; j < 4; j++) {
                    const int p = j >> 1, r = j & 1;
                    mma16816(acc[i][j], ah, bh[p][r], bh[p][r + 2]);
                }
#pragma unroll
                for (int j = 0; j < 4; j++) {
                    const int p = j >> 1, r = j & 1;
                    mma16816(acc[i][j], ah, bl[p][r], bl[p][r + 2]);
                }
#pragma unroll
                for (int j = 0; j < 4; j++) {
                    const int p = j >> 1, r = j & 1;
                    mma16816(acc[i][j], al, bh[p][r], bh[p][r + 2]);
                }
            }
        }
    };

    const int C = K >> 5;
    load_stage(0, 0); cp_commit();
    for (int c = 0; c < C; c++) {
        cp_wait<0>();
        __syncthreads();
        if (c + 1 < C) { load_stage((c + 1) & 1, c + 1); cp_commit(); }
        compute_stage(c & 1);
    }

    // epilogue
    const int mr = m0 + wm * 64;
    const int nc = n0 + wn * 32;
#pragma unroll
    for (int i = 0; i < 4; i++) {
#pragma unroll
        for (int j = 0; j < 4; j++) {
            int n = nc + j * 8 + tig * 2;
            float2 bv = *(const float2*)(bias + n);
            int r_lo = mr + i * 16 + gid;
            int r_hi = r_lo + 8;
            float v00 = acc[i][j][0] + bv.x, v01 = acc[i][j][1] + bv.y;
            float v10 = acc[i][j][2] + bv.x, v11 = acc[i][j][3] + bv.y;
            if (MODE == 1) {
                v00 = fmaxf(v00, 0.f); v01 = fmaxf(v01, 0.f);
                v10 = fmaxf(v10, 0.f); v11 = fmaxf(v11, 0.f);
                __nv_bfloat16 h00 = __float2bfloat16(v00), h01 = __float2bfloat16(v01);
                __nv_bfloat16 h10 = __float2bfloat16(v10), h11 = __float2bfloat16(v11);
                __nv_bfloat162 hi0(h00, h01), hi1(h10, h11);
                __nv_bfloat162 lo0(__float2bfloat16(v00 - __bfloat162float(h00)),
                                   __float2bfloat16(v01 - __bfloat162float(h01)));
                __nv_bfloat162 lo1(__float2bfloat16(v10 - __bfloat162float(h10)),
                                   __float2bfloat16(v11 - __bfloat162float(h11)));
                *(__nv_bfloat162*)(Chi + (size_t)r_lo * ldc + n) = hi0;
                *(__nv_bfloat162*)(Chi + (size_t)r_hi * ldc + n) = hi1;
                *(__nv_bfloat162*)(Clo + (size_t)r_lo * ldc + n) = lo0;
                *(__nv_bfloat162*)(Clo + (size_t)r_hi * ldc + n) = lo1;
            } else {
                *(float2*)(Cf + (size_t)r_lo * ldc + n) = make_float2(v00, v01);
                *(float2*)(Cf + (size_t)r_hi * ldc + n) = make_float2(v10, v11);
            }
        }
    }
}

// ---------------- convex fixed-point + gather (warp per row) ----------------
__global__ __launch_bounds__(256) void convex_gather(
    const float* __restrict__ p, const float* __restrict__ x, float* __restrict__ out) {
    const unsigned FULL = 0xffffffffu;
    int warp = (blockIdx.x * blockDim.x + threadIdx.x) >> 5;
    int lane = threadIdx.x & 31;
    if (warp >= BB) return;

    const float* row = p + (size_t)warp * NF;
    float e[8];
    {
        float4 v0 = *(const float4*)(row + lane * 8);
        float4 v1 = *(const float4*)(row + lane * 8 + 4);
        e[0] = v0.x; e[1] = v0.y; e[2] = v0.z; e[3] = v0.w;
        e[4] = v1.x; e[5] = v1.y; e[6] = v1.z; e[7] = v1.w;
    }
#pragma unroll 2
    for (int it = 0; it < 100; ++it) {
        float lin = __shfl_up_sync(FULL, e[7], 1);
        float rin = __shfl_down_sync(FULL, e[0], 1);
        float n0 = fminf(e[0], 0.5f * (lin + e[1]));
        float n1 = fminf(e[1], 0.5f * (e[0] + e[2]));
        float n2 = fminf(e[2], 0.5f * (e[1] + e[3]));
        float n3 = fminf(e[3], 0.5f * (e[2] + e[4]));
        float n4 = fminf(e[4], 0.5f * (e[3] + e[5]));
        float n5 = fminf(e[5], 0.5f * (e[4] + e[6]));
        float n6 = fminf(e[6], 0.5f * (e[5] + e[7]));
        float n7 = fminf(e[7], 0.5f * (e[6] + rin));
        if (lane == 0)  n0 = e[0];
        if (lane == 31) n7 = e[7];
        e[0] = n0; e[1] = n1; e[2] = n2; e[3] = n3;
        e[4] = n4; e[5] = n5; e[6] = n6; e[7] = n7;
    }
    float q = x[(size_t)warp * 257 + 256];
    int idx = (int)rintf(q * 255.0f);
    idx = min(max(idx, 0), 255);
    int src_lane = idx >> 3, sub = idx & 7;
    float val = 0.f;
#pragma unroll
    for (int j = 0; j < 8; j++) {
        float t = __shfl_sync(FULL, e[j], src_lane);
        if (j == sub) val = t;
    }
    if (lane == 0) out[warp] = val;
}

// ---------------- launch ----------------
extern "C" void kernel_launch(void* const* d_in, const int* in_sizes, int n_in,
                              void* d_out, int out_size) {
    const float* x  = (const float*)d_in[0];
    const float* W1 = (const float*)d_in[1];
    const float* b1 = (const float*)d_in[2];
    const float* W2 = (const float*)d_in[3];
    const float* b2 = (const float*)d_in[4];
    float* out = (float*)d_out;

    void *pa_hi, *pa_lo, *pw1h, *pw1l, *pw2h, *pw2l, *phh, *phl, *pp;
    cudaGetSymbolAddress(&pa_hi, g_a_hi); cudaGetSymbolAddress(&pa_lo, g_a_lo);
    cudaGetSymbolAddress(&pw1h, g_w1_hi); cudaGetSymbolAddress(&pw1l, g_w1_lo);
    cudaGetSymbolAddress(&pw2h, g_w2_hi); cudaGetSymbolAddress(&pw2l, g_w2_lo);
    cudaGetSymbolAddress(&phh, g_h_hi);   cudaGetSymbolAddress(&phl, g_h_lo);
    cudaGetSymbolAddress(&pp, g_p);

    __nv_bfloat16 *a_hi = (__nv_bfloat16*)pa_hi, *a_lo = (__nv_bfloat16*)pa_lo;
    __nv_bfloat16 *w1h = (__nv_bfloat16*)pw1h, *w1l = (__nv_bfloat16*)pw1l;
    __nv_bfloat16 *w2h = (__nv_bfloat16*)pw2h, *w2l = (__nv_bfloat16*)pw2l;
    __nv_bfloat16 *hh = (__nv_bfloat16*)phh, *hl = (__nv_bfloat16*)phl;
    float* prm = (float*)pp;

    cudaFuncSetAttribute(hmma_gemm<0>, cudaFuncAttributeMaxDynamicSharedMemorySize, SMEM_BYTES);
    cudaFuncSetAttribute(hmma_gemm<1>, cudaFuncAttributeMaxDynamicSharedMemorySize, SMEM_BYTES);

    split_x<<<BB * NI / 256, 256>>>(x, a_hi, a_lo);
    split_w<<<NH * NI / 256, 256>>>(W1, w1h, w1l, NH * NI);
    split_w<<<NF * NH / 256, 256>>>(W2, w2h, w2l, NF * NH);

    // GEMM1: h = relu(x @ W1^T + b1) -> bf16 hi/lo
    hmma_gemm<1><<<dim3(NH / 128, BB / 128), 256, SMEM_BYTES>>>(
        a_hi, a_lo, w1h, w1l, b1, NI, NH, nullptr, hh, hl);
    // GEMM2: prm = h @ W2^T + b2 (fp32)
    hmma_gemm<0><<<dim3(NF / 128, BB / 128), 256, SMEM_BYTES>>>(
        hh, hl, w2h, w2l, b2, NH, NF, prm, nullptr, nullptr);

    convex_gather<<<BB / 8, 256>>>(prm, x, out);
}